// round 15
// baseline (speedup 1.0000x reference)
#include <cuda_runtime.h>

#define HW 4096
#define NR 2048
#define NL 16
#define NRC 256
#define SPLITK 16

// ---------------- device scratch ----------------
__device__ float d_S[NR];
__device__ int   d_gcount[NL], d_gstart[NL];
__device__ int   d_nvalid;
__device__ int   d_prow[NR], d_pgrp[NR];
__device__ float d_pwq[NR], d_pbq[NR], d_pwk[NR], d_pbk[NR], d_pwv[NR], d_pbv[NR];
__device__ int   d_pmq[NR], d_pnk[NR], d_pnv[NR];
__device__ float d_cst[NR];
__device__ float d_scores[(long long)NR * NRC];              // 2 MB coeff matrix
__device__ float d_part[(long long)SPLITK * NR * NRC];       // 32 MB splitK partials

// dependency tracking
__device__ int d_ctr;            // global ticket
__device__ int d_doneSC;         // scatter done flag
__device__ int d_doneRS;         // rowsum items completed (target NRS)
__device__ int d_doneS[NL];      // scores items completed (target 64 static)
__device__ int d_doneSM[NL];     // softmax rows completed

#define NWORKERS 296             // 2 CTAs x 148 SMs, all co-resident
#define NRS 256                  // rowsum items (8 rows each)
#define TMAX 2                   // max 128-row tiles per group (gc <= 256)

// static ticket layout
#define T_SC_END 1
#define T_RS_END (T_SC_END + NRS)                       // 257
#define NSC_ITEMS (NL * TMAX * TMAX * SPLITK)           // 1024
#define T_S_END  (T_RS_END + NSC_ITEMS)                 // 1281
#define NSM_ITEMS (NR / 8)                              // 256
#define T_SM_END (T_S_END + NSM_ITEMS)                  // 1537
#define NO_ITEMS (NL * TMAX * 32)                       // 1024
#define T_O_END  (T_SM_END + NO_ITEMS)                  // 2561
#define DONE_S_TGT (TMAX * TMAX * SPLITK)               // 64 per group

// ---------------- f32x2 helpers ----------------
__device__ __forceinline__ unsigned long long dup2(float v) {
    unsigned long long r;
    asm("mov.b64 %0, {%1, %1};" : "=l"(r) : "f"(v));
    return r;
}
__device__ __forceinline__ void fma2(unsigned long long &d, unsigned long long a,
                                     unsigned long long b) {
    asm("fma.rn.f32x2 %0, %1, %2, %0;" : "+l"(d) : "l"(a), "l"(b));
}
__device__ __forceinline__ float2 unpk(unsigned long long v) {
    float2 r;
    asm("mov.b64 {%0, %1}, %2;" : "=f"(r.x), "=f"(r.y) : "l"(v));
    return r;
}

// ---------------- init: counter reset (graph-replay safe) ----------------
__global__ void initKernel() {
    int t = threadIdx.x;
    if (t == 0) { d_ctr = 0; d_doneSC = 0; d_doneRS = 0; }
    if (t < NL) { d_doneS[t] = 0; d_doneSM[t] = 0; }
}

// ================= fused persistent kernel ===============================
// tickets: [0]=scatter  [1..256]=rowsum  [..]=scores  [..]=softmax  [..]=out
__global__ __launch_bounds__(256, 2) void fusedKernel(const float* __restrict__ x,
                                                      const int* __restrict__ labels,
                                                      const float* __restrict__ w,
                                                      const float* __restrict__ bb,
                                                      float* __restrict__ out) {
    __shared__ float Tile[2][8][132];
    __shared__ int Hm[16][16], Pm[16][16], cntS[NL], sstS[NL];
    __shared__ int s_item;
    float (*As)[132] = Tile[0];
    float (*Bs)[132] = Tile[1];

    int tid = threadIdx.x;
    int wid = tid >> 5, lane = tid & 31;
    int ty = tid >> 4, tx = tid & 15;
    int lr = tid >> 1, lk = (tid & 1) * 4;      // tile loaders
    int xk = tid >> 5, xc = (tid & 31) * 4;     // X loader (out)

    for (;;) {
        __syncthreads();
        if (tid == 0) s_item = atomicAdd(&d_ctr, 1);
        __syncthreads();
        int it = s_item;

        if (it < T_SC_END) {
            // ---------- scatter item (one CTA) ----------
            int* sl = (int*)&Tile[0][0][0];            // 2112 ints >= 2048
            for (int j = tid; j < NR; j += 256) sl[j] = labels[j];
            __syncthreads();
            {
                int c = tid >> 4, l = tid & 15;
                int h = 0;
                for (int j = 0; j < 128; j++) h += (sl[c * 128 + j] == l);
                Hm[c][l] = h;
            }
            __syncthreads();
            {
                int c = tid >> 4, l = tid & 15;
                int ps = 0;
                for (int cc = 0; cc < c; cc++) ps += Hm[cc][l];
                Pm[c][l] = ps;
            }
            __syncthreads();
            if (tid < NL) cntS[tid] = Pm[15][tid] + Hm[15][tid];
            __syncthreads();
            if (tid == 0) {
                int s = 0;
                for (int l = 0; l < NL; l++) {
                    sstS[l] = s; d_gstart[l] = s; d_gcount[l] = cntS[l]; s += cntS[l];
                }
                d_nvalid = s;
            }
            __syncthreads();
            for (int i = tid; i < NR; i += 256) {
                int l = sl[i];
                if (l < 0) continue;
                int c = i >> 7;
                int local = 0;
                for (int j = c << 7; j < i; j++) local += (sl[j] == l);
                int pos = sstS[l] + Pm[c][l] + local;
                d_prow[pos] = i;
                d_pgrp[pos] = l;
                int jq = i % 768;            int mq = (i / 768) * 256 + jq / 3;
                int rk = i + 2048; int jk = rk % 768; int nk = (rk / 768) * 256 + jk / 3;
                int rv = i + 4096; int jv = rv % 768; int nv = (rv / 768) * 256 + jv / 3;
                d_pwq[pos] = w[jq]; d_pbq[pos] = bb[jq];
                d_pwk[pos] = w[jk]; d_pbk[pos] = bb[jk];
                d_pwv[pos] = w[jv]; d_pbv[pos] = bb[jv];
                d_pmq[pos] = mq; d_pnk[pos] = nk; d_pnv[pos] = nv;
            }
            __threadfence();
            __syncthreads();
            if (tid == 0) atomicExch(&d_doneSC, 1);

        } else if (it < T_RS_END) {
            // ---------- rowsum item: 8 rows, one per warp ----------
            int m = (it - T_SC_END) * 8 + wid;
            const float4* p = (const float4*)(x + (long long)m * HW);
            float s = 0.f;
            for (int i = lane; i < HW / 4; i += 32) {
                float4 v = p[i];
                s += (v.x + v.y) + (v.z + v.w);
            }
#pragma unroll
            for (int o = 16; o > 0; o >>= 1) s += __shfl_xor_sync(0xffffffffu, s, o);
            if (lane == 0) d_S[m] = s;
            if (labels[m] < 0) {
                float4* op = (float4*)(out + (long long)m * HW);
                float4 z = make_float4(0, 0, 0, 0);
                for (int j = lane; j < HW / 4; j += 32) op[j] = z;
            }
            __threadfence();
            __syncthreads();
            if (tid == 0) atomicAdd(&d_doneRS, 1);

        } else if (it < T_S_END) {
            // ---------- scores item (static map, TMAX=2) ----------
            int si = it - T_RS_END;
            int g  = si >> 6;                     // 64 items per group
            int rem = si & 63;
            int ks = rem & 15;
            int ab = rem >> 4;                    // 0..3
            int a = ab >> 1, b = ab & 1;

            if (tid == 0) {
                while (atomicAdd(&d_doneSC, 0) == 0) __nanosleep(64);
            }
            __syncthreads();
            __threadfence();

            int gc = d_gcount[g];
            int T = (gc + 127) >> 7;
            if (a >= T || b >= T) {
                __syncthreads();
                if (tid == 0) atomicAdd(&d_doneS[g], 1);
                continue;
            }
            int gs = d_gstart[g];
            int a0 = a * 128, b0 = b * 128;
            int k0b = ks * (HW / SPLITK);

            unsigned long long acc[8][4];
#pragma unroll
            for (int r = 0; r < 8; r++)
#pragma unroll
                for (int c = 0; c < 4; c++) acc[r][c] = 0ull;

            const float* ap  = (a0 + lr < gc) ? x + (long long)d_pmq[gs + a0 + lr] * HW : 0;
            const float* bpp = (b0 + lr < gc) ? x + (long long)d_pnk[gs + b0 + lr] * HW : 0;

            for (int kc = 0; kc < (HW / SPLITK) / 8; kc++) {
                int k0 = k0b + kc * 8 + lk;
                float4 va = ap  ? *(const float4*)(ap  + k0) : make_float4(0, 0, 0, 0);
                float4 vb = bpp ? *(const float4*)(bpp + k0) : make_float4(0, 0, 0, 0);
                __syncthreads();
                As[lk + 0][lr] = va.x; As[lk + 1][lr] = va.y;
                As[lk + 2][lr] = va.z; As[lk + 3][lr] = va.w;
                Bs[lk + 0][lr] = vb.x; Bs[lk + 1][lr] = vb.y;
                Bs[lk + 2][lr] = vb.z; Bs[lk + 3][lr] = vb.w;
                __syncthreads();
#pragma unroll
                for (int kk = 0; kk < 8; kk++) {
                    float4 aLo = *(const float4*)&As[kk][ty * 8];
                    float4 aHi = *(const float4*)&As[kk][ty * 8 + 4];
                    ulonglong2 u0 = *(const ulonglong2*)&Bs[kk][tx * 4];
                    ulonglong2 u1 = *(const ulonglong2*)&Bs[kk][64 + tx * 4];
                    unsigned long long bd[4] = { u0.x, u0.y, u1.x, u1.y };
                    unsigned long long ad[8] = { dup2(aLo.x), dup2(aLo.y), dup2(aLo.z), dup2(aLo.w),
                                                 dup2(aHi.x), dup2(aHi.y), dup2(aHi.z), dup2(aHi.w) };
#pragma unroll
                    for (int r = 0; r < 8; r++)
#pragma unroll
                        for (int c = 0; c < 4; c++) fma2(acc[r][c], ad[r], bd[c]);
                }
            }

            long long kbase = (long long)ks * NR * NRC;
#pragma unroll
            for (int r = 0; r < 8; r++) {
                int al = a0 + ty * 8 + r;
                if (al >= gc) continue;
                long long ro = kbase + (long long)(gs + al) * NRC;
#pragma unroll
                for (int c = 0; c < 4; c++) {
                    int col = b0 + ((c < 2) ? tx * 4 + c * 2 : 64 + tx * 4 + (c - 2) * 2);
                    if (col + 1 < gc) {
                        *(unsigned long long*)&d_part[ro + col] = acc[r][c];
                    } else if (col < gc) {
                        d_part[ro + col] = unpk(acc[r][c]).x;
                    }
                }
            }
            __threadfence();
            __syncthreads();
            if (tid == 0) atomicAdd(&d_doneS[g], 1);

        } else if (it < T_SM_END) {
            // ---------- softmax item: 8 rows, one per warp ----------
            int p = (it - T_S_END) * 8 + wid;
            // gate on scatter first (need d_nvalid / d_pgrp)
            if (lane == 0) {
                while (atomicAdd(&d_doneSC, 0) == 0) __nanosleep(64);
            }
            __syncwarp();
            __threadfence();
            if (p < d_nvalid) {
                int g = d_pgrp[p], gs = d_gstart[g], gc = d_gcount[g];
                if (lane == 0) {
                    while (atomicAdd(&d_doneRS, 0) < NRS) __nanosleep(64);
                    while (atomicAdd(&d_doneS[g], 0) < DONE_S_TGT) __nanosleep(64);
                }
                __syncwarp();
                __threadfence();

                long long ro = (long long)p * NRC;
                float wq = d_pwq[p], bq = d_pbq[p];
                float A2 = wq * d_S[d_pmq[p]] + bq * (float)HW;

                float m = -3.4e38f;
                for (int bl = lane; bl < gc; bl += 32) {
                    float gsum = 0.f;
#pragma unroll
                    for (int s = 0; s < SPLITK; s++)
                        gsum += d_part[(long long)s * NR * NRC + ro + bl];
                    int q = gs + bl;
                    float val = d_pwk[q] * (wq * gsum + bq * d_S[d_pnk[q]]) + A2 * d_pbk[q];
                    d_scores[ro + bl] = val;
                    m = fmaxf(m, val);
                }
#pragma unroll
                for (int o = 16; o > 0; o >>= 1)
                    m = fmaxf(m, __shfl_xor_sync(0xffffffffu, m, o));

                float sum = 0.f, cs = 0.f;
                for (int bl = lane; bl < gc; bl += 32) {
                    float e = expf(d_scores[ro + bl] - m);
                    d_scores[ro + bl] = e;
                    sum += e;
                    cs += e * d_pbv[gs + bl];
                }
#pragma unroll
                for (int o = 16; o > 0; o >>= 1) {
                    sum += __shfl_xor_sync(0xffffffffu, sum, o);
                    cs  += __shfl_xor_sync(0xffffffffu, cs, o);
                }
                float inv = 1.0f / sum;
                for (int bl = lane; bl < gc; bl += 32)
                    d_scores[ro + bl] *= inv * d_pwv[gs + bl];
                if (lane == 0) d_cst[p] = cs * inv;

                __threadfence();
                if (lane == 0) atomicAdd(&d_doneSM[g], 1);
            }

        } else if (it < T_O_END) {
            // ---------- out item (static map, TMAX=2) ----------
            int oi = it - T_SM_END;
            int g = oi >> 6;                       // 64 items per group
            int rem = oi & 63;
            int a = rem >> 5;                      // 0..1
            int t0 = (rem & 31) * 128;

            if (tid == 0) {
                while (atomicAdd(&d_doneSC, 0) == 0) __nanosleep(64);
            }
            __syncthreads();
            __threadfence();

            int gc = d_gcount[g];
            int T = (gc + 127) >> 7;
            if (a >= T) continue;
            int gs = d_gstart[g];
            int a0 = a * 128;

            if (tid == 0) {
                while (atomicAdd(&d_doneSM[g], 0) < gc) __nanosleep(64);
            }
            __syncthreads();
            __threadfence();

            unsigned long long acc[8][4];
#pragma unroll
            for (int r = 0; r < 8; r++)
#pragma unroll
                for (int c = 0; c < 4; c++) acc[r][c] = 0ull;

            long long crow = (a0 + lr < gc) ? (long long)(gs + a0 + lr) * NRC : -1;

            for (int b0 = 0; b0 < gc; b0 += 8) {
                float4 vc = make_float4(0, 0, 0, 0);
                if (crow >= 0) {
                    vc = *(const float4*)&d_scores[crow + b0 + lk];
                    if (b0 + lk + 0 >= gc) vc.x = 0.f;
                    if (b0 + lk + 1 >= gc) vc.y = 0.f;
                    if (b0 + lk + 2 >= gc) vc.z = 0.f;
                    if (b0 + lk + 3 >= gc) vc.w = 0.f;
                }
                int bm = b0 + xk;
                int vrow = (bm < gc) ? d_pnv[gs + bm] : 0;
                float4 vx = *(const float4*)&x[(long long)vrow * HW + t0 + xc];
                __syncthreads();
                As[lk + 0][lr] = vc.x; As[lk + 1][lr] = vc.y;
                As[lk + 2][lr] = vc.z; As[lk + 3][lr] = vc.w;
                *(float4*)&Bs[xk][xc] = vx;
                __syncthreads();
#pragma unroll
                for (int kk = 0; kk < 8; kk++) {
                    float4 aLo = *(const float4*)&As[kk][ty * 8];
                    float4 aHi = *(const float4*)&As[kk][ty * 8 + 4];
                    ulonglong2 u0 = *(const ulonglong2*)&Bs[kk][tx * 4];
                    ulonglong2 u1 = *(const ulonglong2*)&Bs[kk][64 + tx * 4];
                    unsigned long long bd[4] = { u0.x, u0.y, u1.x, u1.y };
                    unsigned long long ad[8] = { dup2(aLo.x), dup2(aLo.y), dup2(aLo.z), dup2(aLo.w),
                                                 dup2(aHi.x), dup2(aHi.y), dup2(aHi.z), dup2(aHi.w) };
#pragma unroll
                    for (int r = 0; r < 8; r++)
#pragma unroll
                        for (int c = 0; c < 4; c++) fma2(acc[r][c], ad[r], bd[c]);
                }
            }

#pragma unroll
            for (int r = 0; r < 8; r++) {
                int al = a0 + ty * 8 + r;
                if (al >= gc) continue;
                int p = gs + al;
                int row = d_prow[p];
                float cst = d_cst[p];
                float* op = out + (long long)row * HW + t0;
#pragma unroll
                for (int c = 0; c < 4; c++) {
                    float2 v = unpk(acc[r][c]);
                    int col = (c < 2) ? tx * 4 + c * 2 : 64 + tx * 4 + (c - 2) * 2;
                    op[col]     = v.x + cst;
                    op[col + 1] = v.y + cst;
                }
            }

        } else {
            break;
        }
    }
}

// ---------------- launch ----------------
extern "C" void kernel_launch(void* const* d_in, const int* in_sizes, int n_in,
                              void* d_out, int out_size) {
    const float* x      = (const float*)d_in[0];
    const int*   labels = (const int*)d_in[1];
    const float* w      = (const float*)d_in[2];
    const float* bb     = (const float*)d_in[3];
    float* out = (float*)d_out;

    initKernel<<<1, 32>>>();
    fusedKernel<<<NWORKERS, 256>>>(x, labels, w, bb, out);
    (void)in_sizes; (void)n_in;
}

// round 16
// speedup vs baseline: 1.0808x; 1.0808x over previous
#include <cuda_runtime.h>

#define HW 4096
#define NR 2048
#define NL 16
#define NRC 256
#define SPLITK 16

// ---------------- device scratch ----------------
__device__ float d_S[NR];
__device__ int   d_gcount[NL], d_gstart[NL];
__device__ int   d_nvalid;
__device__ int   d_prow[NR], d_pgrp[NR];
__device__ float d_pwq[NR], d_pbq[NR], d_pwk[NR], d_pbk[NR], d_pwv[NR], d_pbv[NR];
__device__ int   d_pmq[NR], d_pnk[NR], d_pnv[NR];
__device__ float d_cst[NR];
__device__ float d_scores[(long long)NR * NRC];              // 2 MB coeff matrix
__device__ float d_part[(long long)SPLITK * NR * NRC];       // 32 MB splitK partials

#define MAXWS 128
#define MAXWO 64
__device__ int d_wsG[MAXWS], d_wsA[MAXWS], d_wsB[MAXWS], d_nWorkS;
__device__ int d_woG[MAXWO], d_woA[MAXWO], d_nWorkO;

// dependency tracking
__device__ int d_ctr;            // global ticket
__device__ int d_doneRS;         // rowsum items completed (target NRS)
__device__ int d_tgtS[NL];       // scores items per group
__device__ int d_doneS[NL];      // scores items completed
__device__ int d_doneSM[NL];     // softmax rows completed

#define NWORKERS 296             // 2 CTAs x 148 SMs, all co-resident
#define NRS 256                  // rowsum items (8 rows each)

// ---------------- f32x2 helpers ----------------
__device__ __forceinline__ unsigned long long dup2(float v) {
    unsigned long long r;
    asm("mov.b64 %0, {%1, %1};" : "=l"(r) : "f"(v));
    return r;
}
__device__ __forceinline__ void fma2(unsigned long long &d, unsigned long long a,
                                     unsigned long long b) {
    asm("fma.rn.f32x2 %0, %1, %2, %0;" : "+l"(d) : "l"(a), "l"(b));
}
__device__ __forceinline__ float2 unpk(unsigned long long v) {
    float2 r;
    asm("mov.b64 {%0, %1}, %2;" : "=f"(r.x), "=f"(r.y) : "l"(v));
    return r;
}

// ---------------- scatter: setup + grouping + counter reset --------------
// Worklists emitted in LPT order (groups sorted by descending count).
__global__ void scatterKernel(const int* __restrict__ labels,
                              const float* __restrict__ w,
                              const float* __restrict__ bb) {
    __shared__ int sl[NR];
    __shared__ int cnt[NL], sst[NL];
    int t = threadIdx.x;
    if (t < NL) cnt[t] = 0;
    for (int j = t; j < NR; j += 128) sl[j] = labels[j];
    __syncthreads();
    for (int j = t; j < NR; j += 128) {
        int l = sl[j];
        if (l >= 0) atomicAdd(&cnt[l], 1);
    }
    __syncthreads();
    if (t == 0) {
        int s = 0;
        for (int l = 0; l < NL; l++) { sst[l] = s; s += cnt[l]; }
        if (blockIdx.x == 0) {
            d_nvalid = s;
            d_ctr = 0;
            d_doneRS = 0;
            for (int l = 0; l < NL; l++) { d_gcount[l] = cnt[l]; d_gstart[l] = sst[l]; }
            // LPT order: sort group ids by descending count (insertion sort, 16 elems)
            int ord[NL];
            for (int l = 0; l < NL; l++) ord[l] = l;
            for (int i2 = 1; i2 < NL; i2++) {
                int v = ord[i2];
                int j2 = i2 - 1;
                while (j2 >= 0 && cnt[ord[j2]] < cnt[v]) { ord[j2 + 1] = ord[j2]; j2--; }
                ord[j2 + 1] = v;
            }
            int n = 0;
            for (int oi = 0; oi < NL; oi++) {
                int l = ord[oi];
                int T = (cnt[l] + 127) / 128;
                d_doneS[l] = 0;
                d_doneSM[l] = 0;
                d_tgtS[l] = T * T * SPLITK;
                for (int a = 0; a < T; a++)
                    for (int b = 0; b < T; b++)
                        if (n < MAXWS) { d_wsG[n] = l; d_wsA[n] = a; d_wsB[n] = b; n++; }
            }
            d_nWorkS = n;
            n = 0;
            for (int oi = 0; oi < NL; oi++) {
                int l = ord[oi];
                int T = (cnt[l] + 127) / 128;
                for (int a = 0; a < T; a++)
                    if (n < MAXWO) { d_woG[n] = l; d_woA[n] = a; n++; }
            }
            d_nWorkO = n;
        }
    }
    __syncthreads();
    int i = blockIdx.x * 128 + t;
    int l = sl[i];
    if (l < 0) return;
    int rank = 0;
    for (int j = 0; j < i; j++) rank += (sl[j] == l);
    int pos = sst[l] + rank;
    d_prow[pos] = i;
    d_pgrp[pos] = l;
    int jq = i % 768;            int mq = (i / 768) * 256 + jq / 3;
    int rk = i + 2048; int jk = rk % 768; int nk = (rk / 768) * 256 + jk / 3;
    int rv = i + 4096; int jv = rv % 768; int nv = (rv / 768) * 256 + jv / 3;
    d_pwq[pos] = w[jq]; d_pbq[pos] = bb[jq];
    d_pwk[pos] = w[jk]; d_pbk[pos] = bb[jk];
    d_pwv[pos] = w[jv]; d_pbv[pos] = bb[jv];
    d_pmq[pos] = mq; d_pnk[pos] = nk; d_pnv[pos] = nv;
}

// ================= fused persistent kernel ===============================
// ticket stream: [rowsum 256] -> [scores nS] -> [softmax nSM] -> [out nO]
__global__ __launch_bounds__(256, 2) void fusedKernel(const float* __restrict__ x,
                                                      const int* __restrict__ labels,
                                                      float* __restrict__ out) {
    __shared__ float As[8][132], Bs[8][132];
    __shared__ int s_item;
    int tid = threadIdx.x;
    int wid = tid >> 5, lane = tid & 31;
    int ty = tid >> 4, tx = tid & 15;
    int lr = tid >> 1, lk = (tid & 1) * 4;      // tile loaders
    int xk = tid >> 5, xc = (tid & 31) * 4;     // X loader (out)

    int nS  = d_nWorkS * SPLITK;
    int nSM = (d_nvalid + 7) >> 3;
    int nO  = d_nWorkO * 32;

    for (;;) {
        __syncthreads();
        if (tid == 0) s_item = atomicAdd(&d_ctr, 1);
        __syncthreads();
        int it = s_item;

        if (it < NRS) {
            // ---------- rowsum item: 8 rows, one per warp ----------
            int m = it * 8 + wid;
            const float4* p = (const float4*)(x + (long long)m * HW);
            float s = 0.f;
            for (int i = lane; i < HW / 4; i += 32) {
                float4 v = p[i];
                s += (v.x + v.y) + (v.z + v.w);
            }
#pragma unroll
            for (int o = 16; o > 0; o >>= 1) s += __shfl_xor_sync(0xffffffffu, s, o);
            if (lane == 0) d_S[m] = s;
            if (labels[m] < 0) {
                float4* op = (float4*)(out + (long long)m * HW);
                float4 z = make_float4(0, 0, 0, 0);
                for (int j = lane; j < HW / 4; j += 32) op[j] = z;
            }
            __threadfence();
            __syncthreads();
            if (tid == 0) atomicAdd(&d_doneRS, 1);

        } else if (it < NRS + nS) {
            // ---------- scores item ----------
            int si = it - NRS;
            int wi = si >> 4, ks = si & 15;
            int g = d_wsG[wi];
            int gs = d_gstart[g], gc = d_gcount[g];
            int a0 = d_wsA[wi] * 128, b0 = d_wsB[wi] * 128;
            int k0b = ks * (HW / SPLITK);

            unsigned long long acc[8][4];
#pragma unroll
            for (int r = 0; r < 8; r++)
#pragma unroll
                for (int c = 0; c < 4; c++) acc[r][c] = 0ull;

            const float* ap  = (a0 + lr < gc) ? x + (long long)d_pmq[gs + a0 + lr] * HW : 0;
            const float* bpp = (b0 + lr < gc) ? x + (long long)d_pnk[gs + b0 + lr] * HW : 0;

            for (int kc = 0; kc < (HW / SPLITK) / 8; kc++) {
                int k0 = k0b + kc * 8 + lk;
                float4 va = ap  ? *(const float4*)(ap  + k0) : make_float4(0, 0, 0, 0);
                float4 vb = bpp ? *(const float4*)(bpp + k0) : make_float4(0, 0, 0, 0);
                __syncthreads();
                As[lk + 0][lr] = va.x; As[lk + 1][lr] = va.y;
                As[lk + 2][lr] = va.z; As[lk + 3][lr] = va.w;
                Bs[lk + 0][lr] = vb.x; Bs[lk + 1][lr] = vb.y;
                Bs[lk + 2][lr] = vb.z; Bs[lk + 3][lr] = vb.w;
                __syncthreads();
#pragma unroll
                for (int kk = 0; kk < 8; kk++) {
                    float4 aLo = *(const float4*)&As[kk][ty * 8];
                    float4 aHi = *(const float4*)&As[kk][ty * 8 + 4];
                    ulonglong2 u0 = *(const ulonglong2*)&Bs[kk][tx * 4];
                    ulonglong2 u1 = *(const ulonglong2*)&Bs[kk][64 + tx * 4];
                    unsigned long long bd[4] = { u0.x, u0.y, u1.x, u1.y };
                    unsigned long long ad[8] = { dup2(aLo.x), dup2(aLo.y), dup2(aLo.z), dup2(aLo.w),
                                                 dup2(aHi.x), dup2(aHi.y), dup2(aHi.z), dup2(aHi.w) };
#pragma unroll
                    for (int r = 0; r < 8; r++)
#pragma unroll
                        for (int c = 0; c < 4; c++) fma2(acc[r][c], ad[r], bd[c]);
                }
            }

            long long kbase = (long long)ks * NR * NRC;
#pragma unroll
            for (int r = 0; r < 8; r++) {
                int al = a0 + ty * 8 + r;
                if (al >= gc) continue;
                long long ro = kbase + (long long)(gs + al) * NRC;
#pragma unroll
                for (int c = 0; c < 4; c++) {
                    int col = b0 + ((c < 2) ? tx * 4 + c * 2 : 64 + tx * 4 + (c - 2) * 2);
                    if (col + 1 < gc) {
                        *(unsigned long long*)&d_part[ro + col] = acc[r][c];
                    } else if (col < gc) {
                        d_part[ro + col] = unpk(acc[r][c]).x;
                    }
                }
            }
            __threadfence();
            __syncthreads();
            if (tid == 0) atomicAdd(&d_doneS[g], 1);

        } else if (it < NRS + nS + nSM) {
            // ---------- softmax item: 8 rows, one per warp ----------
            int p = (it - NRS - nS) * 8 + wid;
            if (p < d_nvalid) {
                int g = d_pgrp[p], gs = d_gstart[g], gc = d_gcount[g];
                if (lane == 0) {
                    while (atomicAdd(&d_doneRS, 0) < NRS) __nanosleep(64);
                    int tgt = d_tgtS[g];
                    while (atomicAdd(&d_doneS[g], 0) < tgt) __nanosleep(64);
                }
                __syncwarp();
                __threadfence();

                long long ro = (long long)p * NRC;
                float wq = d_pwq[p], bq = d_pbq[p];
                float A2 = wq * d_S[d_pmq[p]] + bq * (float)HW;

                float m = -3.4e38f;
                for (int bl = lane; bl < gc; bl += 32) {
                    float gsum = 0.f;
#pragma unroll
                    for (int s = 0; s < SPLITK; s++)
                        gsum += d_part[(long long)s * NR * NRC + ro + bl];
                    int q = gs + bl;
                    float val = d_pwk[q] * (wq * gsum + bq * d_S[d_pnk[q]]) + A2 * d_pbk[q];
                    d_scores[ro + bl] = val;
                    m = fmaxf(m, val);
                }
#pragma unroll
                for (int o = 16; o > 0; o >>= 1)
                    m = fmaxf(m, __shfl_xor_sync(0xffffffffu, m, o));

                float sum = 0.f, cs = 0.f;
                for (int bl = lane; bl < gc; bl += 32) {
                    float e = expf(d_scores[ro + bl] - m);
                    d_scores[ro + bl] = e;
                    sum += e;
                    cs += e * d_pbv[gs + bl];
                }
#pragma unroll
                for (int o = 16; o > 0; o >>= 1) {
                    sum += __shfl_xor_sync(0xffffffffu, sum, o);
                    cs  += __shfl_xor_sync(0xffffffffu, cs, o);
                }
                float inv = 1.0f / sum;
                for (int bl = lane; bl < gc; bl += 32)
                    d_scores[ro + bl] *= inv * d_pwv[gs + bl];
                if (lane == 0) d_cst[p] = cs * inv;

                __threadfence();
                if (lane == 0) atomicAdd(&d_doneSM[g], 1);
            }

        } else if (it < NRS + nS + nSM + nO) {
            // ---------- out item ----------
            int oi = it - NRS - nS - nSM;
            int wi = oi >> 5;
            int t0 = (oi & 31) * 128;
            int g = d_woG[wi];
            int gs = d_gstart[g], gc = d_gcount[g];
            int a0 = d_woA[wi] * 128;

            if (tid == 0) {
                while (atomicAdd(&d_doneSM[g], 0) < gc) __nanosleep(64);
            }
            __syncthreads();
            __threadfence();

            unsigned long long acc[8][4];
#pragma unroll
            for (int r = 0; r < 8; r++)
#pragma unroll
                for (int c = 0; c < 4; c++) acc[r][c] = 0ull;

            long long crow = (a0 + lr < gc) ? (long long)(gs + a0 + lr) * NRC : -1;

            for (int b0 = 0; b0 < gc; b0 += 8) {
                float4 vc = make_float4(0, 0, 0, 0);
                if (crow >= 0) {
                    vc = *(const float4*)&d_scores[crow + b0 + lk];
                    if (b0 + lk + 0 >= gc) vc.x = 0.f;
                    if (b0 + lk + 1 >= gc) vc.y = 0.f;
                    if (b0 + lk + 2 >= gc) vc.z = 0.f;
                    if (b0 + lk + 3 >= gc) vc.w = 0.f;
                }
                int bm = b0 + xk;
                int vrow = (bm < gc) ? d_pnv[gs + bm] : 0;
                float4 vx = *(const float4*)&x[(long long)vrow * HW + t0 + xc];
                __syncthreads();
                As[lk + 0][lr] = vc.x; As[lk + 1][lr] = vc.y;
                As[lk + 2][lr] = vc.z; As[lk + 3][lr] = vc.w;
                *(float4*)&Bs[xk][xc] = vx;
                __syncthreads();
#pragma unroll
                for (int kk = 0; kk < 8; kk++) {
                    float4 aLo = *(const float4*)&As[kk][ty * 8];
                    float4 aHi = *(const float4*)&As[kk][ty * 8 + 4];
                    ulonglong2 u0 = *(const ulonglong2*)&Bs[kk][tx * 4];
                    ulonglong2 u1 = *(const ulonglong2*)&Bs[kk][64 + tx * 4];
                    unsigned long long bd[4] = { u0.x, u0.y, u1.x, u1.y };
                    unsigned long long ad[8] = { dup2(aLo.x), dup2(aLo.y), dup2(aLo.z), dup2(aLo.w),
                                                 dup2(aHi.x), dup2(aHi.y), dup2(aHi.z), dup2(aHi.w) };
#pragma unroll
                    for (int r = 0; r < 8; r++)
#pragma unroll
                        for (int c = 0; c < 4; c++) fma2(acc[r][c], ad[r], bd[c]);
                }
            }

#pragma unroll
            for (int r = 0; r < 8; r++) {
                int al = a0 + ty * 8 + r;
                if (al >= gc) continue;
                int p = gs + al;
                int row = d_prow[p];
                float cst = d_cst[p];
                float* op = out + (long long)row * HW + t0;
#pragma unroll
                for (int c = 0; c < 4; c++) {
                    float2 v = unpk(acc[r][c]);
                    int col = (c < 2) ? tx * 4 + c * 2 : 64 + tx * 4 + (c - 2) * 2;
                    op[col]     = v.x + cst;
                    op[col + 1] = v.y + cst;
                }
            }

        } else {
            break;
        }
    }
}

// ---------------- launch ----------------
extern "C" void kernel_launch(void* const* d_in, const int* in_sizes, int n_in,
                              void* d_out, int out_size) {
    const float* x      = (const float*)d_in[0];
    const int*   labels = (const int*)d_in[1];
    const float* w      = (const float*)d_in[2];
    const float* bb     = (const float*)d_in[3];
    float* out = (float*)d_out;

    scatterKernel<<<16, 128>>>(labels, w, bb);
    fusedKernel<<<NWORKERS, 256>>>(x, labels, out);
    (void)in_sizes; (void)n_in;
}